// round 14
// baseline (speedup 1.0000x reference)
#include <cuda_runtime.h>
#include <math.h>

// ---------------- problem constants ----------------
#define NB 8
#define NN 2048
#define ND 512
#define NROWS (NB * NN)            // 16384
#define NMATI 33554432             // NROWS * NN

// output layout (floats): cost[8], mu[8,2048], nu[8,2048], pi[8,2048,2048], C[8,2048,2048]
#define OFF_COST 0
#define OFF_MU   8
#define OFF_NU   16392
#define OFF_PI   32776
#define OFF_C    33587208

#define PBLK 148                   // persistent grid (<= SM count, co-resident)
#define NWARPS (PBLK * 32)         // 4736
#define SINK_SMEM ((16384 + 8 * 132) * 4)

// ---------------- device state ----------------
__device__ __align__(16) float g_K[NMATI];      // exp(-C/eps)
__device__ __align__(16) float g_rnx[NROWS];
__device__ __align__(16) float g_rny[NROWS];
__device__ __align__(16) float g_u[NROWS];
__device__ __align__(16) float g_v[NROWS];
__device__ __align__(16) float g_a[NROWS];      // exp(u/eps)
__device__ __align__(16) float g_b[NROWS];      // exp(v/eps)
__device__ __align__(16) float g_delta[NROWS];
__device__ __align__(16) float g_costpart[NROWS];
__device__ int g_done;
__device__ unsigned g_bar_count = 0;
__device__ unsigned g_bar_gen = 0;

// ---------------- f32x2 packed FMA helpers ----------------
#define PACK2(d, lo, hi) \
    asm("mov.b64 %0, {%1, %2};" : "=l"(d) : "r"(lo), "r"(hi))
#define UNPACK2(lo, hi, v) \
    asm("mov.b64 {%0, %1}, %2;" : "=r"(lo), "=r"(hi) : "l"(v))
#define FMA2(d, a, b, c) \
    asm("fma.rn.f32x2 %0, %1, %2, %3;" : "=l"(d) : "l"(a), "l"(b), "l"(c))

// ---------------- grid-wide barrier (persistent kernel) ----------------
__device__ __forceinline__ void grid_sync() {
    __threadfence();
    __syncthreads();
    if (threadIdx.x == 0) {
        unsigned gen = *((volatile unsigned*)&g_bar_gen);
        unsigned arrived = atomicAdd(&g_bar_count, 1u);
        if (arrived == PBLK - 1) {
            g_bar_count = 0;
            __threadfence();
            atomicAdd(&g_bar_gen, 1u);
        } else {
            while (*((volatile unsigned*)&g_bar_gen) == gen) { __nanosleep(64); }
        }
        __threadfence();
    }
    __syncthreads();
}

// ---------------- init: mu/nu outputs + sinkhorn state ----------------
__global__ void init_kernel(float* __restrict__ out) {
    int t = blockIdx.x * blockDim.x + threadIdx.x;
    if (t < NROWS) {
        out[OFF_MU + t] = 4.8828125e-4f;   // 1/2048 exact
        out[OFF_NU + t] = 4.8828125e-4f;
        g_u[t] = 0.0f;
        g_v[t] = 0.0f;
        g_a[t] = 0.0f;
        g_b[t] = 1.0f;
        g_delta[t] = 0.0f;
    }
    if (t == 0) *((volatile int*)&g_done) = 0;
}

// ---------------- inverse row norms ----------------
__global__ void norm_kernel(const float* __restrict__ x, const float* __restrict__ y) {
    int w = (blockIdx.x * blockDim.x + threadIdx.x) >> 5;
    int lane = threadIdx.x & 31;
    if (w >= 2 * NROWS) return;
    const float* p = (w < NROWS) ? (x + (size_t)w * ND)
                                 : (y + (size_t)(w - NROWS) * ND);
    float s = 0.0f;
#pragma unroll
    for (int i = 0; i < 4; ++i) {
        float4 v = *(const float4*)(p + (lane + i * 32) * 4);
        s += v.x * v.x + v.y * v.y + v.z * v.z + v.w * v.w;
    }
#pragma unroll
    for (int o = 16; o; o >>= 1) s += __shfl_xor_sync(0xffffffffu, s, o);
    if (lane == 0) {
        float inv = 1.0f / sqrtf(s);
        if (w < NROWS) g_rnx[w] = inv; else g_rny[w - NROWS] = inv;
    }
}

// ---------------- GEMM: C = 1 - xhat @ yhat^T, K = exp(-10*C) ----------------
__global__ __launch_bounds__(256, 2)
void gemm_kernel(const float* __restrict__ x, const float* __restrict__ y,
                 float* __restrict__ Cout) {
    __shared__ __align__(16) float As[16][132];
    __shared__ __align__(16) float Bs[16][132];
    int b = blockIdx.z;
    int m0 = blockIdx.y * 128, n0 = blockIdx.x * 128;
    const float* A = x + (size_t)b * NN * ND;
    const float* B = y + (size_t)b * NN * ND;
    int tid = threadIdx.x;
    int tx = tid & 15, ty = tid >> 4;

    unsigned long long acc[8][4];
#pragma unroll
    for (int i = 0; i < 8; i++)
#pragma unroll
        for (int j = 0; j < 4; j++) acc[i][j] = 0ULL;

    int r0 = tid >> 2;      // 0..63
    int kq = tid & 3;       // 0..3

    for (int k0 = 0; k0 < ND; k0 += 16) {
#pragma unroll
        for (int l = 0; l < 2; ++l) {
            int row = r0 + l * 64;
            float4 av = *(const float4*)(A + (size_t)(m0 + row) * ND + k0 + kq * 4);
            float sa = g_rnx[b * NN + m0 + row];
            As[kq * 4 + 0][row] = av.x * sa;
            As[kq * 4 + 1][row] = av.y * sa;
            As[kq * 4 + 2][row] = av.z * sa;
            As[kq * 4 + 3][row] = av.w * sa;
            float4 bv = *(const float4*)(B + (size_t)(n0 + row) * ND + k0 + kq * 4);
            float sb = g_rny[b * NN + n0 + row];
            Bs[kq * 4 + 0][row] = bv.x * sb;
            Bs[kq * 4 + 1][row] = bv.y * sb;
            Bs[kq * 4 + 2][row] = bv.z * sb;
            Bs[kq * 4 + 3][row] = bv.w * sb;
        }
        __syncthreads();
#pragma unroll
        for (int k = 0; k < 16; k++) {
            float a8[8], b8[8];
            *(float4*)(a8)     = *(const float4*)(&As[k][ty * 8]);
            *(float4*)(a8 + 4) = *(const float4*)(&As[k][ty * 8 + 4]);
            *(float4*)(b8)     = *(const float4*)(&Bs[k][tx * 8]);
            *(float4*)(b8 + 4) = *(const float4*)(&Bs[k][tx * 8 + 4]);
            unsigned long long bp[4];
#pragma unroll
            for (int j = 0; j < 4; j++)
                PACK2(bp[j], __float_as_uint(b8[2 * j]), __float_as_uint(b8[2 * j + 1]));
#pragma unroll
            for (int i = 0; i < 8; i++) {
                unsigned long long ap;
                unsigned au = __float_as_uint(a8[i]);
                PACK2(ap, au, au);
#pragma unroll
                for (int j = 0; j < 4; j++) FMA2(acc[i][j], ap, bp[j], acc[i][j]);
            }
        }
        __syncthreads();
    }

    // epilogue: C and K = exp(-C/eps)
#pragma unroll
    for (int i = 0; i < 8; i++) {
        int row = m0 + ty * 8 + i;
        float c[8];
#pragma unroll
        for (int j = 0; j < 4; j++) {
            unsigned lo, hi;
            UNPACK2(lo, hi, acc[i][j]);
            c[2 * j]     = 1.0f - __uint_as_float(lo);
            c[2 * j + 1] = 1.0f - __uint_as_float(hi);
        }
        size_t off = ((size_t)b * NN + row) * (size_t)NN + n0 + tx * 8;
        *(float4*)(Cout + off)     = make_float4(c[0], c[1], c[2], c[3]);
        *(float4*)(Cout + off + 4) = make_float4(c[4], c[5], c[6], c[7]);
        float kk[8];
#pragma unroll
        for (int j = 0; j < 8; j++) kk[j] = __expf(-10.0f * c[j]);
        *(float4*)(g_K + off)     = make_float4(kk[0], kk[1], kk[2], kk[3]);
        *(float4*)(g_K + off + 4) = make_float4(kk[4], kk[5], kk[6], kk[7]);
    }
}

// ---------------- persistent Sinkhorn iterations ----------------
__global__ __launch_bounds__(1024, 1)
void sinkhorn_kernel() {
    extern __shared__ float sm[];
    float* stage = sm;                // 16384 floats: b (step1) then a (step2)
    float* red   = sm + 16384;        // 8*132 floats
    __shared__ float rtmp[1024];

    const float LOG_MU = logf(1.0f / 2048.0f + 1e-8f);
    const float MUEXP  = 1.0f / 2048.0f + 1e-8f;

    int tid  = threadIdx.x;
    int bid  = blockIdx.x;
    int lane = tid & 31;
    int warp = tid >> 5;
    int gwarp = bid * 32 + warp;

    for (int iter = 0; iter < 100; ++iter) {
        // ---- stage b into smem (written by other blocks -> bypass L1) ----
        for (int i = tid; i < NROWS; i += 1024) stage[i] = __ldcg(&g_b[i]);
        __syncthreads();

        // ---- step 1: s_i = K_i . b ;  u_new, a_new, delta ----
        for (int row = gwarp; row < NROWS; row += NWARPS) {
            const float* kr = g_K + (size_t)row * NN;
            const float* bb = stage + (row >> 11) * NN;
            float s = 0.0f;
#pragma unroll 4
            for (int it = 0; it < 16; ++it) {
                int j = (lane + it * 32) * 4;
                float4 kv = *(const float4*)(kr + j);
                float4 bv = *(const float4*)(bb + j);
                s += kv.x * bv.x + kv.y * bv.y + kv.z * bv.z + kv.w * bv.w;
            }
#pragma unroll
            for (int o = 16; o; o >>= 1) s += __shfl_xor_sync(0xffffffffu, s, o);
            if (lane == 0) {
                float u_old = g_u[row];                 // written by this thread last iter
                float u_new = 0.1f * (LOG_MU - logf(s));
                g_u[row] = u_new;
                g_a[row] = MUEXP / s;                   // == exp(u_new/eps)
                g_delta[row] = fabsf(u_new - u_old);
            }
        }
        grid_sync();

        // ---- err reduction on block 0 (fixed order -> deterministic) ----
        if (bid == 0) {
            float p = 0.0f;
            for (int i = tid; i < NROWS; i += 1024) p += __ldcg(&g_delta[i]);
            rtmp[tid] = p;
            __syncthreads();
            for (int s2 = 512; s2; s2 >>= 1) {
                if (tid < s2) rtmp[tid] += rtmp[tid + s2];
                __syncthreads();
            }
            if (tid == 0) {
                float err = rtmp[0] * 0.125f;           // mean over 8 batches
                if (err < 0.1f) *((volatile int*)&g_done) = 1;
            }
            __syncthreads();
        }

        // ---- stage a_new into smem ----
        for (int i = tid; i < NROWS; i += 1024) stage[i] = __ldcg(&g_a[i]);
        __syncthreads();

        // ---- step 2: t_j = sum_i K_ij a_i ; v_new, b_new ----
        if (bid < 128) {
            int batch = bid >> 4;
            int colbase = (bid & 15) * 128;
            int sub = tid >> 7, jj = tid & 127;
            const float* kp = g_K + (size_t)batch * NN * NN + colbase + jj;
            const float* ap = stage + batch * NN;
            float acc = 0.0f;
#pragma unroll 4
            for (int i = sub; i < NN; i += 8)
                acc += kp[(size_t)i * NN] * ap[i];
            red[sub * 132 + jj] = acc;
            __syncthreads();
            if (sub == 0) {
                float t = 0.0f;
#pragma unroll
                for (int s2 = 0; s2 < 8; s2++) t += red[s2 * 132 + jj];
                int col = batch * NN + colbase + jj;
                g_v[col] = 0.1f * (LOG_MU - logf(t));   // log_nu == log_mu
                g_b[col] = MUEXP / t;
            }
        }
        grid_sync();
        if (*((volatile int*)&g_done)) break;
    }
}

// ---------------- finalize: pi = exp((u+v-C)/eps), cost partials ----------------
__global__ __launch_bounds__(256)
void finalize_kernel(float* __restrict__ out) {
    int row = blockIdx.x;                 // 0..16383
    int batch = row >> 11;
    const float* Crow = out + OFF_C + (size_t)row * NN;
    float* Prow = out + OFF_PI + (size_t)row * NN;
    float ui = g_u[row];
    const float* vb = g_v + batch * NN;
    float part = 0.0f;
    for (int j4 = threadIdx.x; j4 < NN / 4; j4 += 256) {
        float4 c = *(const float4*)(Crow + j4 * 4);
        float4 v = *(const float4*)(vb + j4 * 4);
        float4 p;
        p.x = __expf((ui + v.x - c.x) * 10.0f);
        p.y = __expf((ui + v.y - c.y) * 10.0f);
        p.z = __expf((ui + v.z - c.z) * 10.0f);
        p.w = __expf((ui + v.w - c.w) * 10.0f);
        *(float4*)(Prow + j4 * 4) = p;
        part += p.x * c.x + p.y * c.y + p.z * c.z + p.w * c.w;
    }
    __shared__ float r[256];
    r[threadIdx.x] = part;
    __syncthreads();
    for (int s = 128; s; s >>= 1) {
        if (threadIdx.x < s) r[threadIdx.x] += r[threadIdx.x + s];
        __syncthreads();
    }
    if (threadIdx.x == 0) g_costpart[row] = r[0];
}

// ---------------- cost: fixed-order per-batch reduce ----------------
__global__ void cost_kernel(float* __restrict__ out) {
    int b = threadIdx.x >> 5;     // 8 warps = 8 batches
    int lane = threadIdx.x & 31;
    float s = 0.0f;
    for (int i = lane; i < NN; i += 32) s += g_costpart[b * NN + i];
#pragma unroll
    for (int o = 16; o; o >>= 1) s += __shfl_xor_sync(0xffffffffu, s, o);
    if (lane == 0) out[OFF_COST + b] = s;
}

// ---------------- launch ----------------
extern "C" void kernel_launch(void* const* d_in, const int* in_sizes, int n_in,
                              void* d_out, int out_size) {
    const float* x = (const float*)d_in[0];
    const float* y = (const float*)d_in[1];
    float* out = (float*)d_out;

    cudaFuncSetAttribute(sinkhorn_kernel,
                         cudaFuncAttributeMaxDynamicSharedMemorySize, SINK_SMEM);

    init_kernel<<<16, 1024>>>(out);
    norm_kernel<<<2048, 512>>>(x, y);
    dim3 gg(16, 16, 8);
    gemm_kernel<<<gg, 256>>>(x, y, out + OFF_C);
    sinkhorn_kernel<<<PBLK, 1024, SINK_SMEM>>>();
    finalize_kernel<<<NROWS, 256>>>(out);
    cost_kernel<<<1, 256>>>(out);
}

// round 15
// speedup vs baseline: 1.0061x; 1.0061x over previous
#include <cuda_runtime.h>
#include <math.h>

// ---------------- problem constants ----------------
#define NB 8
#define NN 2048
#define ND 512
#define NROWS (NB * NN)            // 16384
#define NMATI 33554432             // NROWS * NN

// output layout (floats): cost[8], mu[8,2048], nu[8,2048], pi[8,2048,2048], C[8,2048,2048]
#define OFF_COST 0
#define OFF_MU   8
#define OFF_NU   16392
#define OFF_PI   32776
#define OFF_C    33587208

#define PBLK 148                   // persistent grid (<= SM count, co-resident)
#define NWARPS (PBLK * 32)         // 4736
#define SINK_SMEM ((16384 + 8 * 132) * 4)

// ---------------- device state ----------------
__device__ __align__(16) float g_K[NMATI];      // exp(-C/eps)
__device__ __align__(16) float g_rnx[NROWS];
__device__ __align__(16) float g_rny[NROWS];
__device__ __align__(16) float g_u[NROWS];
__device__ __align__(16) float g_v[NROWS];
__device__ __align__(16) float g_a[NROWS];      // exp(u/eps)
__device__ __align__(16) float g_b[NROWS];      // exp(v/eps)
__device__ __align__(16) float g_delta[NROWS];
__device__ __align__(16) float g_costpart[NROWS];
__device__ int g_done;
__device__ unsigned g_bar_count = 0;
__device__ unsigned g_bar_gen = 0;

// ---------------- f32x2 packed FMA helpers ----------------
#define PACK2(d, lo, hi) \
    asm("mov.b64 %0, {%1, %2};" : "=l"(d) : "r"(lo), "r"(hi))
#define UNPACK2(lo, hi, v) \
    asm("mov.b64 {%0, %1}, %2;" : "=r"(lo), "=r"(hi) : "l"(v))
#define FMA2(d, a, b, c) \
    asm("fma.rn.f32x2 %0, %1, %2, %3;" : "=l"(d) : "l"(a), "l"(b), "l"(c))

// ---------------- grid-wide barrier (persistent kernel) ----------------
__device__ __forceinline__ void grid_sync() {
    __threadfence();
    __syncthreads();
    if (threadIdx.x == 0) {
        unsigned gen = *((volatile unsigned*)&g_bar_gen);
        unsigned arrived = atomicAdd(&g_bar_count, 1u);
        if (arrived == PBLK - 1) {
            g_bar_count = 0;
            __threadfence();
            atomicAdd(&g_bar_gen, 1u);
        } else {
            while (*((volatile unsigned*)&g_bar_gen) == gen) { __nanosleep(64); }
        }
        __threadfence();
    }
    __syncthreads();
}

// ---------------- init: mu/nu outputs + sinkhorn state ----------------
__global__ void init_kernel(float* __restrict__ out) {
    int t = blockIdx.x * blockDim.x + threadIdx.x;
    if (t < NROWS) {
        out[OFF_MU + t] = 4.8828125e-4f;   // 1/2048 exact
        out[OFF_NU + t] = 4.8828125e-4f;
        g_u[t] = 0.0f;
        g_v[t] = 0.0f;
        g_a[t] = 0.0f;
        g_b[t] = 1.0f;
        g_delta[t] = 0.0f;
    }
    if (t == 0) *((volatile int*)&g_done) = 0;
}

// ---------------- inverse row norms ----------------
__global__ void norm_kernel(const float* __restrict__ x, const float* __restrict__ y) {
    int w = (blockIdx.x * blockDim.x + threadIdx.x) >> 5;
    int lane = threadIdx.x & 31;
    if (w >= 2 * NROWS) return;
    const float* p = (w < NROWS) ? (x + (size_t)w * ND)
                                 : (y + (size_t)(w - NROWS) * ND);
    float s = 0.0f;
#pragma unroll
    for (int i = 0; i < 4; ++i) {
        float4 v = *(const float4*)(p + (lane + i * 32) * 4);
        s += v.x * v.x + v.y * v.y + v.z * v.z + v.w * v.w;
    }
#pragma unroll
    for (int o = 16; o; o >>= 1) s += __shfl_xor_sync(0xffffffffu, s, o);
    if (lane == 0) {
        float inv = 1.0f / sqrtf(s);
        if (w < NROWS) g_rnx[w] = inv; else g_rny[w - NROWS] = inv;
    }
}

// ---------------- GEMM: C = 1 - xhat @ yhat^T, K = exp(-10*C) ----------------
__global__ __launch_bounds__(256, 2)
void gemm_kernel(const float* __restrict__ x, const float* __restrict__ y,
                 float* __restrict__ Cout) {
    __shared__ __align__(16) float As[16][132];
    __shared__ __align__(16) float Bs[16][132];
    int b = blockIdx.z;
    int m0 = blockIdx.y * 128, n0 = blockIdx.x * 128;
    const float* A = x + (size_t)b * NN * ND;
    const float* B = y + (size_t)b * NN * ND;
    int tid = threadIdx.x;
    int tx = tid & 15, ty = tid >> 4;

    unsigned long long acc[8][4];
#pragma unroll
    for (int i = 0; i < 8; i++)
#pragma unroll
        for (int j = 0; j < 4; j++) acc[i][j] = 0ULL;

    int r0 = tid >> 2;      // 0..63
    int kq = tid & 3;       // 0..3

    for (int k0 = 0; k0 < ND; k0 += 16) {
#pragma unroll
        for (int l = 0; l < 2; ++l) {
            int row = r0 + l * 64;
            float4 av = *(const float4*)(A + (size_t)(m0 + row) * ND + k0 + kq * 4);
            float sa = g_rnx[b * NN + m0 + row];
            As[kq * 4 + 0][row] = av.x * sa;
            As[kq * 4 + 1][row] = av.y * sa;
            As[kq * 4 + 2][row] = av.z * sa;
            As[kq * 4 + 3][row] = av.w * sa;
            float4 bv = *(const float4*)(B + (size_t)(n0 + row) * ND + k0 + kq * 4);
            float sb = g_rny[b * NN + n0 + row];
            Bs[kq * 4 + 0][row] = bv.x * sb;
            Bs[kq * 4 + 1][row] = bv.y * sb;
            Bs[kq * 4 + 2][row] = bv.z * sb;
            Bs[kq * 4 + 3][row] = bv.w * sb;
        }
        __syncthreads();
#pragma unroll
        for (int k = 0; k < 16; k++) {
            float a8[8], b8[8];
            *(float4*)(a8)     = *(const float4*)(&As[k][ty * 8]);
            *(float4*)(a8 + 4) = *(const float4*)(&As[k][ty * 8 + 4]);
            *(float4*)(b8)     = *(const float4*)(&Bs[k][tx * 8]);
            *(float4*)(b8 + 4) = *(const float4*)(&Bs[k][tx * 8 + 4]);
            unsigned long long bp[4];
#pragma unroll
            for (int j = 0; j < 4; j++)
                PACK2(bp[j], __float_as_uint(b8[2 * j]), __float_as_uint(b8[2 * j + 1]));
#pragma unroll
            for (int i = 0; i < 8; i++) {
                unsigned long long ap;
                unsigned au = __float_as_uint(a8[i]);
                PACK2(ap, au, au);
#pragma unroll
                for (int j = 0; j < 4; j++) FMA2(acc[i][j], ap, bp[j], acc[i][j]);
            }
        }
        __syncthreads();
    }

    // epilogue: C and K = exp(-C/eps)
#pragma unroll
    for (int i = 0; i < 8; i++) {
        int row = m0 + ty * 8 + i;
        float c[8];
#pragma unroll
        for (int j = 0; j < 4; j++) {
            unsigned lo, hi;
            UNPACK2(lo, hi, acc[i][j]);
            c[2 * j]     = 1.0f - __uint_as_float(lo);
            c[2 * j + 1] = 1.0f - __uint_as_float(hi);
        }
        size_t off = ((size_t)b * NN + row) * (size_t)NN + n0 + tx * 8;
        *(float4*)(Cout + off)     = make_float4(c[0], c[1], c[2], c[3]);
        *(float4*)(Cout + off + 4) = make_float4(c[4], c[5], c[6], c[7]);
        float kk[8];
#pragma unroll
        for (int j = 0; j < 8; j++) kk[j] = __expf(-10.0f * c[j]);
        *(float4*)(g_K + off)     = make_float4(kk[0], kk[1], kk[2], kk[3]);
        *(float4*)(g_K + off + 4) = make_float4(kk[4], kk[5], kk[6], kk[7]);
    }
}

// ---------------- persistent Sinkhorn iterations ----------------
__global__ __launch_bounds__(1024, 1)
void sinkhorn_kernel() {
    extern __shared__ float sm[];
    float* stage = sm;                // 16384 floats: b (step1) then a (step2)
    float* red   = sm + 16384;        // 8*132 floats
    __shared__ float rtmp[1024];

    const float LOG_MU = logf(1.0f / 2048.0f + 1e-8f);
    const float MUEXP  = 1.0f / 2048.0f + 1e-8f;

    int tid  = threadIdx.x;
    int bid  = blockIdx.x;
    int lane = tid & 31;
    int warp = tid >> 5;
    int gwarp = bid * 32 + warp;

    for (int iter = 0; iter < 100; ++iter) {
        // ---- stage b into smem (written by other blocks -> bypass L1) ----
        for (int i = tid; i < NROWS; i += 1024) stage[i] = __ldcg(&g_b[i]);
        __syncthreads();

        // ---- step 1: s_i = K_i . b ;  u_new, a_new, delta ----
        for (int row = gwarp; row < NROWS; row += NWARPS) {
            const float* kr = g_K + (size_t)row * NN;
            const float* bb = stage + (row >> 11) * NN;
            float s = 0.0f;
#pragma unroll 4
            for (int it = 0; it < 16; ++it) {
                int j = (lane + it * 32) * 4;
                float4 kv = *(const float4*)(kr + j);
                float4 bv = *(const float4*)(bb + j);
                s += kv.x * bv.x + kv.y * bv.y + kv.z * bv.z + kv.w * bv.w;
            }
#pragma unroll
            for (int o = 16; o; o >>= 1) s += __shfl_xor_sync(0xffffffffu, s, o);
            if (lane == 0) {
                float u_old = g_u[row];                 // written by this thread last iter
                float u_new = 0.1f * (LOG_MU - logf(s));
                g_u[row] = u_new;
                g_a[row] = MUEXP / s;                   // == exp(u_new/eps)
                g_delta[row] = fabsf(u_new - u_old);
            }
        }
        grid_sync();

        // ---- err reduction on block 0 (fixed order -> deterministic) ----
        if (bid == 0) {
            float p = 0.0f;
            for (int i = tid; i < NROWS; i += 1024) p += __ldcg(&g_delta[i]);
            rtmp[tid] = p;
            __syncthreads();
            for (int s2 = 512; s2; s2 >>= 1) {
                if (tid < s2) rtmp[tid] += rtmp[tid + s2];
                __syncthreads();
            }
            if (tid == 0) {
                float err = rtmp[0] * 0.125f;           // mean over 8 batches
                if (err < 0.1f) *((volatile int*)&g_done) = 1;
            }
            __syncthreads();
        }

        // ---- stage a_new into smem ----
        for (int i = tid; i < NROWS; i += 1024) stage[i] = __ldcg(&g_a[i]);
        __syncthreads();

        // ---- step 2: t_j = sum_i K_ij a_i ; v_new, b_new ----
        if (bid < 128) {
            int batch = bid >> 4;
            int colbase = (bid & 15) * 128;
            int sub = tid >> 7, jj = tid & 127;
            const float* kp = g_K + (size_t)batch * NN * NN + colbase + jj;
            const float* ap = stage + batch * NN;
            float acc = 0.0f;
#pragma unroll 4
            for (int i = sub; i < NN; i += 8)
                acc += kp[(size_t)i * NN] * ap[i];
            red[sub * 132 + jj] = acc;
            __syncthreads();
            if (sub == 0) {
                float t = 0.0f;
#pragma unroll
                for (int s2 = 0; s2 < 8; s2++) t += red[s2 * 132 + jj];
                int col = batch * NN + colbase + jj;
                g_v[col] = 0.1f * (LOG_MU - logf(t));   // log_nu == log_mu
                g_b[col] = MUEXP / t;
            }
        }
        grid_sync();
        if (*((volatile int*)&g_done)) break;
    }
}

// ---------------- finalize: pi = exp((u+v-C)/eps), cost partials ----------------
__global__ __launch_bounds__(256)
void finalize_kernel(float* __restrict__ out) {
    int row = blockIdx.x;                 // 0..16383
    int batch = row >> 11;
    const float* Crow = out + OFF_C + (size_t)row * NN;
    float* Prow = out + OFF_PI + (size_t)row * NN;
    float ui = g_u[row];
    const float* vb = g_v + batch * NN;
    float part = 0.0f;
    for (int j4 = threadIdx.x; j4 < NN / 4; j4 += 256) {
        float4 c = *(const float4*)(Crow + j4 * 4);
        float4 v = *(const float4*)(vb + j4 * 4);
        float4 p;
        p.x = __expf((ui + v.x - c.x) * 10.0f);
        p.y = __expf((ui + v.y - c.y) * 10.0f);
        p.z = __expf((ui + v.z - c.z) * 10.0f);
        p.w = __expf((ui + v.w - c.w) * 10.0f);
        *(float4*)(Prow + j4 * 4) = p;
        part += p.x * c.x + p.y * c.y + p.z * c.z + p.w * c.w;
    }
    __shared__ float r[256];
    r[threadIdx.x] = part;
    __syncthreads();
    for (int s = 128; s; s >>= 1) {
        if (threadIdx.x < s) r[threadIdx.x] += r[threadIdx.x + s];
        __syncthreads();
    }
    if (threadIdx.x == 0) g_costpart[row] = r[0];
}

// ---------------- cost: fixed-order per-batch reduce ----------------
__global__ void cost_kernel(float* __restrict__ out) {
    int b = threadIdx.x >> 5;     // 8 warps = 8 batches
    int lane = threadIdx.x & 31;
    float s = 0.0f;
    for (int i = lane; i < NN; i += 32) s += g_costpart[b * NN + i];
#pragma unroll
    for (int o = 16; o; o >>= 1) s += __shfl_xor_sync(0xffffffffu, s, o);
    if (lane == 0) out[OFF_COST + b] = s;
}

// ---------------- launch ----------------
extern "C" void kernel_launch(void* const* d_in, const int* in_sizes, int n_in,
                              void* d_out, int out_size) {
    const float* x = (const float*)d_in[0];
    const float* y = (const float*)d_in[1];
    float* out = (float*)d_out;

    cudaFuncSetAttribute(sinkhorn_kernel,
                         cudaFuncAttributeMaxDynamicSharedMemorySize, SINK_SMEM);

    init_kernel<<<16, 1024>>>(out);
    norm_kernel<<<2048, 512>>>(x, y);
    dim3 gg(16, 16, 8);
    gemm_kernel<<<gg, 256>>>(x, y, out + OFF_C);
    sinkhorn_kernel<<<PBLK, 1024, SINK_SMEM>>>();
    finalize_kernel<<<NROWS, 256>>>(out);
    cost_kernel<<<1, 256>>>(out);
}